// round 4
// baseline (speedup 1.0000x reference)
#include <cuda_runtime.h>
#include <math.h>

#define B_DIM 64
#define N_DIM 4096
#define K_DIM 32
#define U_DIM 16
#define NUM_STEPS 8
#define BN (B_DIM * N_DIM)            // 262144 sites
#define NU (N_DIM * U_DIM)            // 65536 (GEMM K)
#define H1 256
#define H2 32
#define NCLS 2

#define NSPLIT 256
#define KCHUNK (NU / NSPLIT)          // 256

// scratch (device globals: allocation-free)
__device__ float g_h[BN * U_DIM];               // 16 MB: h outputs (B, N*U) row-major
__device__ float g_part[NSPLIT * B_DIM * H1];   // 16 MB: split-K partials

__device__ __forceinline__ float sigmoid_fast(float v) {
    return __fdividef(1.0f, 1.0f + __expf(-v));
}
__device__ __forceinline__ float tanh_fast(float v) {
    float z = __expf(-2.0f * v);
    return __fdividef(1.0f - z, 1.0f + z);
}

// ---------------------------------------------------------------------------
// Kernel 1: per-site UGRNN recurrence. One thread = one (b, n) site.
// ---------------------------------------------------------------------------
__global__ __launch_bounds__(256, 1)
void ugrnn_kernel(const float* __restrict__ inputs,
                  const float* __restrict__ Wn,
                  const float* __restrict__ Wg,
                  const float* __restrict__ Ug,
                  const float* __restrict__ bg,
                  const float* __restrict__ Wc,
                  const float* __restrict__ Uc,
                  const float* __restrict__ bc,
                  const float* __restrict__ We,
                  const float* __restrict__ be)
{
    __shared__ float sWn[K_DIM * U_DIM];   // 512
    __shared__ float sWg[U_DIM * U_DIM];
    __shared__ float sUg[U_DIM * U_DIM];
    __shared__ float sWc[U_DIM * U_DIM];
    __shared__ float sUc[U_DIM * U_DIM];
    __shared__ float sWe[U_DIM * U_DIM];
    __shared__ float sb[3 * U_DIM];

    const int tid = threadIdx.x;
    for (int i = tid; i < K_DIM * U_DIM; i += 256) sWn[i] = Wn[i];
    if (tid < 256) {
        sWg[tid] = Wg[tid]; sUg[tid] = Ug[tid];
        sWc[tid] = Wc[tid]; sUc[tid] = Uc[tid];
        sWe[tid] = We[tid];
    }
    if (tid < U_DIM) {
        sb[tid]              = bg[tid];
        sb[U_DIM + tid]      = bc[tid];
        sb[2 * U_DIM + tid]  = be[tid];
    }
    __syncthreads();

    const int site = blockIdx.x * 256 + tid;   // 0 .. BN-1
    const float* __restrict__ row = inputs + (long long)site * (K_DIM + 2);

    const float h0 = __ldg(&row[0]);
    const float e0 = __ldg(&row[K_DIM + 1]);

    // m[u] = sum_k neigh[k] * Wn[k][u]
    float m[U_DIM];
#pragma unroll
    for (int u = 0; u < U_DIM; u++) m[u] = 0.0f;
#pragma unroll 8
    for (int k = 0; k < K_DIM; k++) {
        float nk = __ldg(&row[1 + k]);
#pragma unroll
        for (int u = 0; u < U_DIM; u++)
            m[u] = fmaf(nk, sWn[k * U_DIM + u], m[u]);
    }

    float h[U_DIM], e[U_DIM];
#pragma unroll
    for (int u = 0; u < U_DIM; u++) { h[u] = h0; e[u] = e0; }

#pragma unroll 1
    for (int step = 0; step < NUM_STEPS; step++) {
        float x[U_DIM];
#pragma unroll
        for (int u = 0; u < U_DIM; u++) x[u] = m[u] + e[u];

        float ag[U_DIM], ac[U_DIM], ae[U_DIM];
#pragma unroll
        for (int u = 0; u < U_DIM; u++) {
            ag[u] = sb[u];
            ac[u] = sb[U_DIM + u];
            ae[u] = sb[2 * U_DIM + u];
        }

#pragma unroll
        for (int j = 0; j < U_DIM; j++) {
            const float xj = x[j];
            const float hj = h[j];
#pragma unroll
            for (int u = 0; u < U_DIM; u++) {
                ag[u] = fmaf(xj, sWg[j * U_DIM + u], ag[u]);
                ag[u] = fmaf(hj, sUg[j * U_DIM + u], ag[u]);
                ac[u] = fmaf(xj, sWc[j * U_DIM + u], ac[u]);
                ac[u] = fmaf(hj, sUc[j * U_DIM + u], ac[u]);
                ae[u] = fmaf(xj, sWe[j * U_DIM + u], ae[u]);
            }
        }

#pragma unroll
        for (int u = 0; u < U_DIM; u++) {
            float g = sigmoid_fast(ag[u]);
            float c = tanh_fast(ac[u]);
            h[u] = fmaf(g, h[u] - c, c);      // g*h + (1-g)*c
            e[u] = tanh_fast(ae[u]);
        }
    }

    float* __restrict__ dst = g_h + (long long)site * U_DIM;
#pragma unroll
    for (int u = 0; u < U_DIM; u++) dst[u] = h[u];
}

// ---------------------------------------------------------------------------
// Kernel 2: split-K GEMM: part[split] += A(64 x KCHUNK) * W1(KCHUNK x 256)
// A[b][k] = g_h[b*NU + k]. Classic 8x8 register tiling.
// ---------------------------------------------------------------------------
__global__ __launch_bounds__(256, 2)
void gemm1_kernel(const float* __restrict__ W1)
{
    __shared__ float As[16][B_DIM];     // [k][row]
    __shared__ float Bs[16][H1];        // [k][col]

    const int split = blockIdx.x;
    const int k0 = split * KCHUNK;
    const int tid = threadIdx.x;
    const int tm = tid >> 5;            // 0..7  -> rows tm*8 .. tm*8+7
    const int tn = tid & 31;            // 0..31 -> cols tn*8 .. tn*8+7

    float acc[8][8];
#pragma unroll
    for (int i = 0; i < 8; i++)
#pragma unroll
        for (int j = 0; j < 8; j++) acc[i][j] = 0.0f;

    // A-load indices: 64 rows x 16 k = 1024 floats, 256 threads x float4 (along k)
    const int ar = tid >> 2;             // row 0..63
    const int akq = (tid & 3) * 4;       // k offset 0,4,8,12

    for (int kk = 0; kk < KCHUNK; kk += 16) {
        // load A tile (transposed into As[k][row])
        float4 av = *(const float4*)&g_h[(long long)ar * NU + k0 + kk + akq];
        As[akq + 0][ar] = av.x;
        As[akq + 1][ar] = av.y;
        As[akq + 2][ar] = av.z;
        As[akq + 3][ar] = av.w;
        // load B tile: 16 x 256 = 4096 floats = 1024 float4, 4 per thread
#pragma unroll
        for (int i = 0; i < 4; i++) {
            int idx = tid + i * 256;          // float4 index
            int kr = idx >> 6;                // 0..15
            int cq = (idx & 63) * 4;          // col 0..252
            float4 bv = *(const float4*)&W1[(long long)(k0 + kk + kr) * H1 + cq];
            *(float4*)&Bs[kr][cq] = bv;
        }
        __syncthreads();

#pragma unroll
        for (int k = 0; k < 16; k++) {
            float a[8], b[8];
            float4 a0 = *(const float4*)&As[k][tm * 8];
            float4 a1 = *(const float4*)&As[k][tm * 8 + 4];
            a[0] = a0.x; a[1] = a0.y; a[2] = a0.z; a[3] = a0.w;
            a[4] = a1.x; a[5] = a1.y; a[6] = a1.z; a[7] = a1.w;
            float4 b0 = *(const float4*)&Bs[k][tn * 8];
            float4 b1 = *(const float4*)&Bs[k][tn * 8 + 4];
            b[0] = b0.x; b[1] = b0.y; b[2] = b0.z; b[3] = b0.w;
            b[4] = b1.x; b[5] = b1.y; b[6] = b1.z; b[7] = b1.w;
#pragma unroll
            for (int i = 0; i < 8; i++)
#pragma unroll
                for (int j = 0; j < 8; j++)
                    acc[i][j] = fmaf(a[i], b[j], acc[i][j]);
        }
        __syncthreads();
    }

    float* __restrict__ out = g_part + (long long)split * (B_DIM * H1);
#pragma unroll
    for (int i = 0; i < 8; i++) {
        int r = tm * 8 + i;
#pragma unroll
        for (int j = 0; j < 8; j++)
            out[r * H1 + tn * 8 + j] = acc[i][j];
    }
}

// ---------------------------------------------------------------------------
// Kernel 3: reduce split-K partials + bias + relu, then layers 2/3 + softmax.
// One block per batch row b.
// ---------------------------------------------------------------------------
__global__ __launch_bounds__(256, 1)
void mlp_kernel(const float* __restrict__ b1,
                const float* __restrict__ W2,
                const float* __restrict__ b2,
                const float* __restrict__ W3,
                const float* __restrict__ b3,
                float* __restrict__ out)
{
    __shared__ float sv[H1];
    __shared__ float s2[H2];
    __shared__ float sl[NCLS];

    const int b = blockIdx.x;
    const int o = threadIdx.x;

    // reduce over splits (stride H1*B between splits for fixed (b,o))
    const float* __restrict__ p = g_part + (long long)b * H1 + o;
    float s0 = 0.f, s1 = 0.f, s2a = 0.f, s3 = 0.f;
#pragma unroll 4
    for (int s = 0; s < NSPLIT; s += 4) {
        s0 += p[(long long)(s + 0) * (B_DIM * H1)];
        s1 += p[(long long)(s + 1) * (B_DIM * H1)];
        s2a += p[(long long)(s + 2) * (B_DIM * H1)];
        s3 += p[(long long)(s + 3) * (B_DIM * H1)];
    }
    float v = b1[o] + ((s0 + s1) + (s2a + s3));
    sv[o] = fmaxf(v, 0.0f);
    __syncthreads();

    if (o < H2) {
        float a = b2[o];
#pragma unroll 8
        for (int i = 0; i < H1; i++)
            a = fmaf(sv[i], W2[i * H2 + o], a);
        s2[o] = fmaxf(a, 0.0f);
    }
    __syncthreads();

    if (o < NCLS) {
        float a = b3[o];
#pragma unroll
        for (int j = 0; j < H2; j++)
            a = fmaf(s2[j], W3[j * NCLS + o], a);
        sl[o] = a;
    }
    __syncthreads();

    if (o == 0) {
        float mx = fmaxf(sl[0], sl[1]);
        float e0 = __expf(sl[0] - mx);
        float e1 = __expf(sl[1] - mx);
        float inv = __fdividef(1.0f, e0 + e1);
        out[b * NCLS + 0] = e0 * inv;
        out[b * NCLS + 1] = e1 * inv;
    }
}

// ---------------------------------------------------------------------------
extern "C" void kernel_launch(void* const* d_in, const int* in_sizes, int n_in,
                              void* d_out, int out_size)
{
    const float* inputs = (const float*)d_in[0];
    const float* Wn = (const float*)d_in[1];
    const float* Wg = (const float*)d_in[2];
    const float* Ug = (const float*)d_in[3];
    const float* bg = (const float*)d_in[4];
    const float* Wc = (const float*)d_in[5];
    const float* Uc = (const float*)d_in[6];
    const float* bc = (const float*)d_in[7];
    const float* We = (const float*)d_in[8];
    const float* be = (const float*)d_in[9];
    const float* W1 = (const float*)d_in[10];
    const float* b1 = (const float*)d_in[11];
    const float* W2 = (const float*)d_in[12];
    const float* b2 = (const float*)d_in[13];
    const float* W3 = (const float*)d_in[14];
    const float* b3 = (const float*)d_in[15];
    float* out = (float*)d_out;

    ugrnn_kernel<<<BN / 256, 256>>>(inputs, Wn, Wg, Ug, bg, Wc, Uc, bc, We, be);
    gemm1_kernel<<<NSPLIT, 256>>>(W1);
    mlp_kernel<<<B_DIM, 256>>>(b1, W2, b2, W3, b3, out);
}

// round 6
// speedup vs baseline: 1.1588x; 1.1588x over previous
#include <cuda_runtime.h>
#include <math.h>

#define B_DIM 64
#define N_DIM 4096
#define K_DIM 32
#define U_DIM 16
#define NUM_STEPS 8
#define BN (B_DIM * N_DIM)            // 262144 sites
#define NU (N_DIM * U_DIM)            // 65536 (GEMM K)
#define H1 256
#define H2 32
#define NCLS 2

#define NSPLIT 256
#define KCHUNK (NU / NSPLIT)          // 256

// scratch (device globals: allocation-free)
__device__ float g_h[BN * U_DIM];               // 16 MB: h outputs (B, N*U) row-major
__device__ float g_part[NSPLIT * B_DIM * H1];   // 16 MB: split-K partials

__device__ __forceinline__ float sigmoid_fast(float v) {
    return __fdividef(1.0f, 1.0f + __expf(-v));
}
__device__ __forceinline__ float tanh_fast(float v) {
    float z = __expf(-2.0f * v);
    return __fdividef(1.0f - z, 1.0f + z);
}

// ---------------------------------------------------------------------------
// Kernel 1: per-site UGRNN recurrence. One thread = one (b, n) site.
// Register-pressure-optimized: gate GEMVs done in 3 sequential passes so only
// ONE 16-wide accumulator is live at a time; x overwrites e in place.
// ---------------------------------------------------------------------------
__global__ __launch_bounds__(256, 2)
void ugrnn_kernel(const float* __restrict__ inputs,
                  const float* __restrict__ Wn,
                  const float* __restrict__ Wg,
                  const float* __restrict__ Ug,
                  const float* __restrict__ bg,
                  const float* __restrict__ Wc,
                  const float* __restrict__ Uc,
                  const float* __restrict__ bc,
                  const float* __restrict__ We,
                  const float* __restrict__ be)
{
    __shared__ __align__(16) float sWn[K_DIM * U_DIM];   // 512
    __shared__ __align__(16) float sWg[U_DIM * U_DIM];
    __shared__ __align__(16) float sUg[U_DIM * U_DIM];
    __shared__ __align__(16) float sWc[U_DIM * U_DIM];
    __shared__ __align__(16) float sUc[U_DIM * U_DIM];
    __shared__ __align__(16) float sWe[U_DIM * U_DIM];
    __shared__ __align__(16) float sb[3 * U_DIM];

    const int tid = threadIdx.x;
    for (int i = tid; i < K_DIM * U_DIM; i += 256) sWn[i] = Wn[i];
    if (tid < 256) {
        sWg[tid] = Wg[tid]; sUg[tid] = Ug[tid];
        sWc[tid] = Wc[tid]; sUc[tid] = Uc[tid];
        sWe[tid] = We[tid];
    }
    if (tid < U_DIM) {
        sb[tid]              = bg[tid];
        sb[U_DIM + tid]      = bc[tid];
        sb[2 * U_DIM + tid]  = be[tid];
    }
    __syncthreads();

    const int site = blockIdx.x * 256 + tid;   // 0 .. BN-1
    const float* __restrict__ row = inputs + (long long)site * (K_DIM + 2);

    const float h0 = __ldg(&row[0]);
    const float e0 = __ldg(&row[K_DIM + 1]);

    // m[u] = sum_k neigh[k] * Wn[k][u]
    float m[U_DIM];
#pragma unroll
    for (int u = 0; u < U_DIM; u++) m[u] = 0.0f;
#pragma unroll 4
    for (int k = 0; k < K_DIM; k++) {
        float nk = __ldg(&row[1 + k]);
        const float4* wr = (const float4*)&sWn[k * U_DIM];
#pragma unroll
        for (int q = 0; q < 4; q++) {
            float4 w = wr[q];
            m[q * 4 + 0] = fmaf(nk, w.x, m[q * 4 + 0]);
            m[q * 4 + 1] = fmaf(nk, w.y, m[q * 4 + 1]);
            m[q * 4 + 2] = fmaf(nk, w.z, m[q * 4 + 2]);
            m[q * 4 + 3] = fmaf(nk, w.w, m[q * 4 + 3]);
        }
    }

    float h[U_DIM], e[U_DIM];
#pragma unroll
    for (int u = 0; u < U_DIM; u++) { h[u] = h0; e[u] = e0; }

#pragma unroll 1
    for (int step = 0; step < NUM_STEPS; step++) {
        // x = m + e, stored IN PLACE into e (e dead until end of step)
#pragma unroll
        for (int u = 0; u < U_DIM; u++) e[u] = m[u] + e[u];

        // ---- pass 1: g = sigmoid(x@Wg + h@Ug + bg) ----
        float g[U_DIM];
#pragma unroll
        for (int u = 0; u < U_DIM; u++) g[u] = sb[u];
#pragma unroll
        for (int j = 0; j < U_DIM; j++) {
            const float xj = e[j];
            const float hj = h[j];
            const float4* wgr = (const float4*)&sWg[j * U_DIM];
            const float4* ugr = (const float4*)&sUg[j * U_DIM];
#pragma unroll
            for (int q = 0; q < 4; q++) {
                float4 wv = wgr[q];
                float4 uv = ugr[q];
                g[q * 4 + 0] = fmaf(xj, wv.x, fmaf(hj, uv.x, g[q * 4 + 0]));
                g[q * 4 + 1] = fmaf(xj, wv.y, fmaf(hj, uv.y, g[q * 4 + 1]));
                g[q * 4 + 2] = fmaf(xj, wv.z, fmaf(hj, uv.z, g[q * 4 + 2]));
                g[q * 4 + 3] = fmaf(xj, wv.w, fmaf(hj, uv.w, g[q * 4 + 3]));
            }
        }
#pragma unroll
        for (int u = 0; u < U_DIM; u++) g[u] = sigmoid_fast(g[u]);

        // ---- pass 2: c = tanh(x@Wc + h@Uc + bc); h = g*h + (1-g)*c ----
        {
            float acc[U_DIM];
#pragma unroll
            for (int u = 0; u < U_DIM; u++) acc[u] = sb[U_DIM + u];
#pragma unroll
            for (int j = 0; j < U_DIM; j++) {
                const float xj = e[j];
                const float hj = h[j];
                const float4* wcr = (const float4*)&sWc[j * U_DIM];
                const float4* ucr = (const float4*)&sUc[j * U_DIM];
#pragma unroll
                for (int q = 0; q < 4; q++) {
                    float4 wv = wcr[q];
                    float4 uv = ucr[q];
                    acc[q * 4 + 0] = fmaf(xj, wv.x, fmaf(hj, uv.x, acc[q * 4 + 0]));
                    acc[q * 4 + 1] = fmaf(xj, wv.y, fmaf(hj, uv.y, acc[q * 4 + 1]));
                    acc[q * 4 + 2] = fmaf(xj, wv.z, fmaf(hj, uv.z, acc[q * 4 + 2]));
                    acc[q * 4 + 3] = fmaf(xj, wv.w, fmaf(hj, uv.w, acc[q * 4 + 3]));
                }
            }
#pragma unroll
            for (int u = 0; u < U_DIM; u++) {
                float c = tanh_fast(acc[u]);
                h[u] = fmaf(g[u], h[u] - c, c);     // g*h + (1-g)*c
            }
        }

        // ---- pass 3: e = tanh(x@We + be)  (x still in e regs; new e overwrites after) ----
        {
            float acc[U_DIM];
#pragma unroll
            for (int u = 0; u < U_DIM; u++) acc[u] = sb[2 * U_DIM + u];
#pragma unroll
            for (int j = 0; j < U_DIM; j++) {
                const float xj = e[j];
                const float4* wer = (const float4*)&sWe[j * U_DIM];
#pragma unroll
                for (int q = 0; q < 4; q++) {
                    float4 wv = wer[q];
                    acc[q * 4 + 0] = fmaf(xj, wv.x, acc[q * 4 + 0]);
                    acc[q * 4 + 1] = fmaf(xj, wv.y, acc[q * 4 + 1]);
                    acc[q * 4 + 2] = fmaf(xj, wv.z, acc[q * 4 + 2]);
                    acc[q * 4 + 3] = fmaf(xj, wv.w, acc[q * 4 + 3]);
                }
            }
#pragma unroll
            for (int u = 0; u < U_DIM; u++) e[u] = tanh_fast(acc[u]);
        }
    }

    float* __restrict__ dst = g_h + (long long)site * U_DIM;
#pragma unroll
    for (int q = 0; q < 4; q++) {
        float4 v = make_float4(h[q * 4 + 0], h[q * 4 + 1], h[q * 4 + 2], h[q * 4 + 3]);
        *(float4*)&dst[q * 4] = v;
    }
}

// ---------------------------------------------------------------------------
// Kernel 2: split-K GEMM: part[split] = A(64 x KCHUNK) * W1(KCHUNK x 256)
// ---------------------------------------------------------------------------
__global__ __launch_bounds__(256, 2)
void gemm1_kernel(const float* __restrict__ W1)
{
    __shared__ float As[16][B_DIM];     // [k][row]
    __shared__ float Bs[16][H1];        // [k][col]

    const int split = blockIdx.x;
    const int k0 = split * KCHUNK;
    const int tid = threadIdx.x;
    const int tm = tid >> 5;            // 0..7  -> rows tm*8 .. tm*8+7
    const int tn = tid & 31;            // 0..31 -> cols tn*8 .. tn*8+7

    float acc[8][8];
#pragma unroll
    for (int i = 0; i < 8; i++)
#pragma unroll
        for (int j = 0; j < 8; j++) acc[i][j] = 0.0f;

    const int ar = tid >> 2;             // row 0..63
    const int akq = (tid & 3) * 4;       // k offset 0,4,8,12

    for (int kk = 0; kk < KCHUNK; kk += 16) {
        float4 av = *(const float4*)&g_h[(long long)ar * NU + k0 + kk + akq];
        As[akq + 0][ar] = av.x;
        As[akq + 1][ar] = av.y;
        As[akq + 2][ar] = av.z;
        As[akq + 3][ar] = av.w;
#pragma unroll
        for (int i = 0; i < 4; i++) {
            int idx = tid + i * 256;          // float4 index
            int kr = idx >> 6;                // 0..15
            int cq = (idx & 63) * 4;          // col 0..252
            float4 bv = *(const float4*)&W1[(long long)(k0 + kk + kr) * H1 + cq];
            *(float4*)&Bs[kr][cq] = bv;
        }
        __syncthreads();

#pragma unroll
        for (int k = 0; k < 16; k++) {
            float a[8], b[8];
            float4 a0 = *(const float4*)&As[k][tm * 8];
            float4 a1 = *(const float4*)&As[k][tm * 8 + 4];
            a[0] = a0.x; a[1] = a0.y; a[2] = a0.z; a[3] = a0.w;
            a[4] = a1.x; a[5] = a1.y; a[6] = a1.z; a[7] = a1.w;
            float4 b0 = *(const float4*)&Bs[k][tn * 8];
            float4 b1 = *(const float4*)&Bs[k][tn * 8 + 4];
            b[0] = b0.x; b[1] = b0.y; b[2] = b0.z; b[3] = b0.w;
            b[4] = b1.x; b[5] = b1.y; b[6] = b1.z; b[7] = b1.w;
#pragma unroll
            for (int i = 0; i < 8; i++)
#pragma unroll
                for (int j = 0; j < 8; j++)
                    acc[i][j] = fmaf(a[i], b[j], acc[i][j]);
        }
        __syncthreads();
    }

    float* __restrict__ out = g_part + (long long)split * (B_DIM * H1);
#pragma unroll
    for (int i = 0; i < 8; i++) {
        int r = tm * 8 + i;
#pragma unroll
        for (int j = 0; j < 8; j++)
            out[r * H1 + tn * 8 + j] = acc[i][j];
    }
}

// ---------------------------------------------------------------------------
// Kernel 3: reduce split-K partials + bias + relu, then layers 2/3 + softmax.
// ---------------------------------------------------------------------------
__global__ __launch_bounds__(256, 1)
void mlp_kernel(const float* __restrict__ b1,
                const float* __restrict__ W2,
                const float* __restrict__ b2,
                const float* __restrict__ W3,
                const float* __restrict__ b3,
                float* __restrict__ out)
{
    __shared__ float sv[H1];
    __shared__ float s2[H2];
    __shared__ float sl[NCLS];

    const int b = blockIdx.x;
    const int o = threadIdx.x;

    const float* __restrict__ p = g_part + (long long)b * H1 + o;
    float s0 = 0.f, s1 = 0.f, s2a = 0.f, s3 = 0.f;
#pragma unroll 4
    for (int s = 0; s < NSPLIT; s += 4) {
        s0  += p[(long long)(s + 0) * (B_DIM * H1)];
        s1  += p[(long long)(s + 1) * (B_DIM * H1)];
        s2a += p[(long long)(s + 2) * (B_DIM * H1)];
        s3  += p[(long long)(s + 3) * (B_DIM * H1)];
    }
    float v = b1[o] + ((s0 + s1) + (s2a + s3));
    sv[o] = fmaxf(v, 0.0f);
    __syncthreads();

    if (o < H2) {
        float a = b2[o];
#pragma unroll 8
        for (int i = 0; i < H1; i++)
            a = fmaf(sv[i], W2[i * H2 + o], a);
        s2[o] = fmaxf(a, 0.0f);
    }
    __syncthreads();

    if (o < NCLS) {
        float a = b3[o];
#pragma unroll
        for (int j = 0; j < H2; j++)
            a = fmaf(s2[j], W3[j * NCLS + o], a);
        sl[o] = a;
    }
    __syncthreads();

    if (o == 0) {
        float mx = fmaxf(sl[0], sl[1]);
        float e0 = __expf(sl[0] - mx);
        float e1 = __expf(sl[1] - mx);
        float inv = __fdividef(1.0f, e0 + e1);
        out[b * NCLS + 0] = e0 * inv;
        out[b * NCLS + 1] = e1 * inv;
    }
}

// ---------------------------------------------------------------------------
extern "C" void kernel_launch(void* const* d_in, const int* in_sizes, int n_in,
                              void* d_out, int out_size)
{
    const float* inputs = (const float*)d_in[0];
    const float* Wn = (const float*)d_in[1];
    const float* Wg = (const float*)d_in[2];
    const float* Ug = (const float*)d_in[3];
    const float* bg = (const float*)d_in[4];
    const float* Wc = (const float*)d_in[5];
    const float* Uc = (const float*)d_in[6];
    const float* bc = (const float*)d_in[7];
    const float* We = (const float*)d_in[8];
    const float* be = (const float*)d_in[9];
    const float* W1 = (const float*)d_in[10];
    const float* b1 = (const float*)d_in[11];
    const float* W2 = (const float*)d_in[12];
    const float* b2 = (const float*)d_in[13];
    const float* W3 = (const float*)d_in[14];
    const float* b3 = (const float*)d_in[15];
    float* out = (float*)d_out;

    ugrnn_kernel<<<BN / 256, 256>>>(inputs, Wn, Wg, Ug, bg, Wc, Uc, bc, We, be);
    gemm1_kernel<<<NSPLIT, 256>>>(W1);
    mlp_kernel<<<B_DIM, 256>>>(b1, W2, b2, W3, b3, out);
}

// round 7
// speedup vs baseline: 5.5396x; 4.7806x over previous
#include <cuda_runtime.h>
#include <math.h>

#define B_DIM 64
#define N_DIM 4096
#define K_DIM 32
#define U_DIM 16
#define NUM_STEPS 8
#define BN (B_DIM * N_DIM)            // 262144 sites
#define NU (N_DIM * U_DIM)            // 65536 (GEMM K)
#define H1 256
#define H2 32
#define NCLS 2
#define ROWLEN (K_DIM + 2)            // 34

#define NSPLIT 256
#define KCHUNK (NU / NSPLIT)          // 256

// scratch (device globals: allocation-free)
__device__ float g_h[BN * U_DIM];               // 16 MB: h outputs (B, N*U) row-major
__device__ float g_part[NSPLIT * B_DIM * H1];   // 16 MB: split-K partials

__device__ __forceinline__ float sigmoid_fast(float v) {
    return __fdividef(1.0f, 1.0f + __expf(-v));
}
__device__ __forceinline__ float tanh_fast(float v) {
    float z = __expf(-2.0f * v);
    return __fdividef(1.0f - z, 1.0f + z);
}

// ---------------------------------------------------------------------------
// Kernel 1: per-site UGRNN recurrence. FOUR threads per site; thread p owns
// units 4p..4p+3. Per-step, all-16 x/h are gathered via __shfl_sync(width=4).
// Register footprint ~80 -> no spills, FMA-pipe bound.
// ---------------------------------------------------------------------------
__global__ __launch_bounds__(256, 2)
void ugrnn_kernel(const float* __restrict__ inputs,
                  const float* __restrict__ Wn,
                  const float* __restrict__ Wg,
                  const float* __restrict__ Ug,
                  const float* __restrict__ bg,
                  const float* __restrict__ Wc,
                  const float* __restrict__ Uc,
                  const float* __restrict__ bc,
                  const float* __restrict__ We,
                  const float* __restrict__ be)
{
    __shared__ __align__(16) float sWn[K_DIM * U_DIM];   // 512
    __shared__ __align__(16) float sWg[U_DIM * U_DIM];
    __shared__ __align__(16) float sUg[U_DIM * U_DIM];
    __shared__ __align__(16) float sWc[U_DIM * U_DIM];
    __shared__ __align__(16) float sUc[U_DIM * U_DIM];
    __shared__ __align__(16) float sWe[U_DIM * U_DIM];
    __shared__ __align__(16) float sb[3 * U_DIM];

    const int tid = threadIdx.x;
    for (int i = tid; i < K_DIM * U_DIM; i += 256) sWn[i] = Wn[i];
    if (tid < 256) {
        sWg[tid] = Wg[tid]; sUg[tid] = Ug[tid];
        sWc[tid] = Wc[tid]; sUc[tid] = Uc[tid];
        sWe[tid] = We[tid];
    }
    if (tid < U_DIM) {
        sb[tid]              = bg[tid];
        sb[U_DIM + tid]      = bc[tid];
        sb[2 * U_DIM + tid]  = be[tid];
    }
    __syncthreads();

    const int gthread = blockIdx.x * 256 + tid;
    const int site = gthread >> 2;              // 0 .. BN-1
    const int p = tid & 3;                      // unit group: cols 4p..4p+3
    const int pc = p * 4;
    const float* __restrict__ row = inputs + (long long)site * ROWLEN;

    const float h0 = __ldg(&row[0]);
    const float e0 = __ldg(&row[K_DIM + 1]);

    // m[i] = sum_k neigh[k] * Wn[k][pc+i]
    float m[4] = {0.f, 0.f, 0.f, 0.f};
#pragma unroll 8
    for (int k = 0; k < K_DIM; k++) {
        float nk = __ldg(&row[1 + k]);
        float4 w = *(const float4*)&sWn[k * U_DIM + pc];
        m[0] = fmaf(nk, w.x, m[0]);
        m[1] = fmaf(nk, w.y, m[1]);
        m[2] = fmaf(nk, w.z, m[2]);
        m[3] = fmaf(nk, w.w, m[3]);
    }

    float h[4], e[4];
#pragma unroll
    for (int i = 0; i < 4; i++) { h[i] = h0; e[i] = e0; }

    const float4 bgv = *(const float4*)&sb[pc];
    const float4 bcv = *(const float4*)&sb[U_DIM + pc];
    const float4 bev = *(const float4*)&sb[2 * U_DIM + pc];

#pragma unroll 1
    for (int step = 0; step < NUM_STEPS; step++) {
        // x = m + e (own 4 units)
        float x[4];
#pragma unroll
        for (int i = 0; i < 4; i++) x[i] = m[i] + e[i];

        // gather all 16 x and h for this site via 4-lane shuffles
        float xa[U_DIM], ha[U_DIM];
#pragma unroll
        for (int jq = 0; jq < 4; jq++) {
#pragma unroll
            for (int ju = 0; ju < 4; ju++) {
                xa[jq * 4 + ju] = __shfl_sync(0xffffffffu, x[ju], jq, 4);
                ha[jq * 4 + ju] = __shfl_sync(0xffffffffu, h[ju], jq, 4);
            }
        }

        // ---- g = sigmoid(x@Wg + h@Ug + bg), own 4 cols ----
        float g[4] = {bgv.x, bgv.y, bgv.z, bgv.w};
#pragma unroll
        for (int j = 0; j < U_DIM; j++) {
            const float xj = xa[j];
            const float hj = ha[j];
            float4 wv = *(const float4*)&sWg[j * U_DIM + pc];
            float4 uv = *(const float4*)&sUg[j * U_DIM + pc];
            g[0] = fmaf(xj, wv.x, fmaf(hj, uv.x, g[0]));
            g[1] = fmaf(xj, wv.y, fmaf(hj, uv.y, g[1]));
            g[2] = fmaf(xj, wv.z, fmaf(hj, uv.z, g[2]));
            g[3] = fmaf(xj, wv.w, fmaf(hj, uv.w, g[3]));
        }
#pragma unroll
        for (int i = 0; i < 4; i++) g[i] = sigmoid_fast(g[i]);

        // ---- c = tanh(x@Wc + h@Uc + bc); h = g*h + (1-g)*c ----
        {
            float acc[4] = {bcv.x, bcv.y, bcv.z, bcv.w};
#pragma unroll
            for (int j = 0; j < U_DIM; j++) {
                const float xj = xa[j];
                const float hj = ha[j];
                float4 wv = *(const float4*)&sWc[j * U_DIM + pc];
                float4 uv = *(const float4*)&sUc[j * U_DIM + pc];
                acc[0] = fmaf(xj, wv.x, fmaf(hj, uv.x, acc[0]));
                acc[1] = fmaf(xj, wv.y, fmaf(hj, uv.y, acc[1]));
                acc[2] = fmaf(xj, wv.z, fmaf(hj, uv.z, acc[2]));
                acc[3] = fmaf(xj, wv.w, fmaf(hj, uv.w, acc[3]));
            }
#pragma unroll
            for (int i = 0; i < 4; i++) {
                float c = tanh_fast(acc[i]);
                h[i] = fmaf(g[i], h[i] - c, c);   // g*h + (1-g)*c
            }
        }

        // ---- e = tanh(x@We + be) ----
        {
            float acc[4] = {bev.x, bev.y, bev.z, bev.w};
#pragma unroll
            for (int j = 0; j < U_DIM; j++) {
                const float xj = xa[j];
                float4 wv = *(const float4*)&sWe[j * U_DIM + pc];
                acc[0] = fmaf(xj, wv.x, acc[0]);
                acc[1] = fmaf(xj, wv.y, acc[1]);
                acc[2] = fmaf(xj, wv.z, acc[2]);
                acc[3] = fmaf(xj, wv.w, acc[3]);
            }
#pragma unroll
            for (int i = 0; i < 4; i++) e[i] = tanh_fast(acc[i]);
        }
    }

    // store own 4 h values (float4, contiguous per lane)
    float4 hv = make_float4(h[0], h[1], h[2], h[3]);
    *(float4*)&g_h[(long long)site * U_DIM + pc] = hv;
}

// ---------------------------------------------------------------------------
// Kernel 2: split-K GEMM: part[split] = A(64 x KCHUNK) * W1(KCHUNK x 256)
// ---------------------------------------------------------------------------
__global__ __launch_bounds__(256, 2)
void gemm1_kernel(const float* __restrict__ W1)
{
    __shared__ float As[16][B_DIM];     // [k][row]
    __shared__ float Bs[16][H1];        // [k][col]

    const int split = blockIdx.x;
    const int k0 = split * KCHUNK;
    const int tid = threadIdx.x;
    const int tm = tid >> 5;            // 0..7  -> rows tm*8 .. tm*8+7
    const int tn = tid & 31;            // 0..31 -> cols tn*8 .. tn*8+7

    float acc[8][8];
#pragma unroll
    for (int i = 0; i < 8; i++)
#pragma unroll
        for (int j = 0; j < 8; j++) acc[i][j] = 0.0f;

    const int ar = tid >> 2;             // row 0..63
    const int akq = (tid & 3) * 4;       // k offset 0,4,8,12

    for (int kk = 0; kk < KCHUNK; kk += 16) {
        float4 av = *(const float4*)&g_h[(long long)ar * NU + k0 + kk + akq];
        As[akq + 0][ar] = av.x;
        As[akq + 1][ar] = av.y;
        As[akq + 2][ar] = av.z;
        As[akq + 3][ar] = av.w;
#pragma unroll
        for (int i = 0; i < 4; i++) {
            int idx = tid + i * 256;          // float4 index
            int kr = idx >> 6;                // 0..15
            int cq = (idx & 63) * 4;          // col 0..252
            float4 bv = *(const float4*)&W1[(long long)(k0 + kk + kr) * H1 + cq];
            *(float4*)&Bs[kr][cq] = bv;
        }
        __syncthreads();

#pragma unroll
        for (int k = 0; k < 16; k++) {
            float a[8], b[8];
            float4 a0 = *(const float4*)&As[k][tm * 8];
            float4 a1 = *(const float4*)&As[k][tm * 8 + 4];
            a[0] = a0.x; a[1] = a0.y; a[2] = a0.z; a[3] = a0.w;
            a[4] = a1.x; a[5] = a1.y; a[6] = a1.z; a[7] = a1.w;
            float4 b0 = *(const float4*)&Bs[k][tn * 8];
            float4 b1 = *(const float4*)&Bs[k][tn * 8 + 4];
            b[0] = b0.x; b[1] = b0.y; b[2] = b0.z; b[3] = b0.w;
            b[4] = b1.x; b[5] = b1.y; b[6] = b1.z; b[7] = b1.w;
#pragma unroll
            for (int i = 0; i < 8; i++)
#pragma unroll
                for (int j = 0; j < 8; j++)
                    acc[i][j] = fmaf(a[i], b[j], acc[i][j]);
        }
        __syncthreads();
    }

    float* __restrict__ out = g_part + (long long)split * (B_DIM * H1);
#pragma unroll
    for (int i = 0; i < 8; i++) {
        int r = tm * 8 + i;
#pragma unroll
        for (int j = 0; j < 8; j++)
            out[r * H1 + tn * 8 + j] = acc[i][j];
    }
}

// ---------------------------------------------------------------------------
// Kernel 3: reduce split-K partials + bias + relu, then layers 2/3 + softmax.
// ---------------------------------------------------------------------------
__global__ __launch_bounds__(256, 1)
void mlp_kernel(const float* __restrict__ b1,
                const float* __restrict__ W2,
                const float* __restrict__ b2,
                const float* __restrict__ W3,
                const float* __restrict__ b3,
                float* __restrict__ out)
{
    __shared__ float sv[H1];
    __shared__ float s2[H2];
    __shared__ float sl[NCLS];

    const int b = blockIdx.x;
    const int o = threadIdx.x;

    const float* __restrict__ p = g_part + (long long)b * H1 + o;
    float s0 = 0.f, s1 = 0.f, s2a = 0.f, s3 = 0.f;
#pragma unroll 4
    for (int s = 0; s < NSPLIT; s += 4) {
        s0  += p[(long long)(s + 0) * (B_DIM * H1)];
        s1  += p[(long long)(s + 1) * (B_DIM * H1)];
        s2a += p[(long long)(s + 2) * (B_DIM * H1)];
        s3  += p[(long long)(s + 3) * (B_DIM * H1)];
    }
    float v = b1[o] + ((s0 + s1) + (s2a + s3));
    sv[o] = fmaxf(v, 0.0f);
    __syncthreads();

    if (o < H2) {
        float a = b2[o];
#pragma unroll 8
        for (int i = 0; i < H1; i++)
            a = fmaf(sv[i], W2[i * H2 + o], a);
        s2[o] = fmaxf(a, 0.0f);
    }
    __syncthreads();

    if (o < NCLS) {
        float a = b3[o];
#pragma unroll
        for (int j = 0; j < H2; j++)
            a = fmaf(s2[j], W3[j * NCLS + o], a);
        sl[o] = a;
    }
    __syncthreads();

    if (o == 0) {
        float mx = fmaxf(sl[0], sl[1]);
        float e0 = __expf(sl[0] - mx);
        float e1 = __expf(sl[1] - mx);
        float inv = __fdividef(1.0f, e0 + e1);
        out[b * NCLS + 0] = e0 * inv;
        out[b * NCLS + 1] = e1 * inv;
    }
}

// ---------------------------------------------------------------------------
extern "C" void kernel_launch(void* const* d_in, const int* in_sizes, int n_in,
                              void* d_out, int out_size)
{
    const float* inputs = (const float*)d_in[0];
    const float* Wn = (const float*)d_in[1];
    const float* Wg = (const float*)d_in[2];
    const float* Ug = (const float*)d_in[3];
    const float* bg = (const float*)d_in[4];
    const float* Wc = (const float*)d_in[5];
    const float* Uc = (const float*)d_in[6];
    const float* bc = (const float*)d_in[7];
    const float* We = (const float*)d_in[8];
    const float* be = (const float*)d_in[9];
    const float* W1 = (const float*)d_in[10];
    const float* b1 = (const float*)d_in[11];
    const float* W2 = (const float*)d_in[12];
    const float* b2 = (const float*)d_in[13];
    const float* W3 = (const float*)d_in[14];
    const float* b3 = (const float*)d_in[15];
    float* out = (float*)d_out;

    ugrnn_kernel<<<(BN * 4) / 256, 256>>>(inputs, Wn, Wg, Ug, bg, Wc, Uc, bc, We, be);
    gemm1_kernel<<<NSPLIT, 256>>>(W1);
    mlp_kernel<<<B_DIM, 256>>>(b1, W2, b2, W3, b3, out);
}